// round 3
// baseline (speedup 1.0000x reference)
#include <cuda_runtime.h>
#include <math.h>

// ============================================================================
// ImplicitMLP: GFF(128) -> FMM(256->256,r=70) -> FMM(256->128,r=10)
//              -> 128->32 -> 32->16 -> 16->3, fp32, ReLU between layers.
// TWO points per thread (weight LDS amortized across both), TPB=384 so each
// SM runs 12 warps (round-2 bottleneck: issue=36% at 8 warps, latency-bound).
// __launch_bounds__(384,1) caps regs at 170 (144-reg accumulator set fits).
// Packed f32x2 FMA throughout. Weights staged transposed/padded in smem.
// ============================================================================

#define TPB 384

typedef unsigned long long u64;

__device__ __forceinline__ u64 f2fma(u64 a, u64 b, u64 c) {
    u64 d;
    asm("fma.rn.f32x2 %0, %1, %2, %3;" : "=l"(d) : "l"(a), "l"(b), "l"(c));
    return d;
}
__device__ __forceinline__ u64 f2add(u64 a, u64 b) {
    u64 d;
    asm("add.rn.f32x2 %0, %1, %2;" : "=l"(d) : "l"(a), "l"(b));
    return d;
}
__device__ __forceinline__ u64 pack2(float lo, float hi) {
    u64 r;
    asm("mov.b64 %0, {%1, %2};" : "=l"(r) : "f"(lo), "f"(hi));
    return r;
}
__device__ __forceinline__ float2 unpack2(u64 v) {
    float lo, hi;
    asm("mov.b64 {%0, %1}, %2;" : "=f"(lo), "=f"(hi) : "l"(v));
    return make_float2(lo, hi);
}

// ---- shared memory layout (float offsets) ----
#define OFF_BP 0
#define OFF_RS 256
#define OFF_RC 9472
#define OFF_L1 18688
#define OFF_R2 37120
#define OFF_L2 40192
#define OFF_W3 41728
#define OFF_W4 45824
#define OFF_W5 46336
#define OFF_B1 46400
#define OFF_B2 46656
#define OFF_B3 46784
#define OFF_B4 46816
#define OFF_B5 46832
#define SMEM_FLOATS 46840

__global__ void __launch_bounds__(TPB, 1) implicit_mlp_kernel(
    const float* __restrict__ coords, const float* __restrict__ Bmat,
    const float* __restrict__ L1, const float* __restrict__ R1, const float* __restrict__ b1,
    const float* __restrict__ L2, const float* __restrict__ R2, const float* __restrict__ b2,
    const float* __restrict__ W3, const float* __restrict__ b3,
    const float* __restrict__ W4, const float* __restrict__ b4,
    const float* __restrict__ W5, const float* __restrict__ b5,
    float* __restrict__ out, int npts)
{
    extern __shared__ float sm[];
    const int tid = threadIdx.x;
    const float TWOPI = 6.283185307179586f;

    // ---- stage transposed/padded weights into smem ----
    for (int i = tid; i < 128; i += TPB) {
        sm[OFF_BP + 2 * i]     = Bmat[i] * TWOPI;
        sm[OFF_BP + 2 * i + 1] = Bmat[128 + i] * TWOPI;
    }
    for (int idx = tid; idx < 128 * 72; idx += TPB) {
        int i = idx / 72, r = idx - i * 72;
        float vs = 0.f, vc = 0.f;
        if (r < 70) { vs = R1[r * 256 + i]; vc = R1[r * 256 + 128 + i]; }
        sm[OFF_RS + idx] = vs;
        sm[OFF_RC + idx] = vc;
    }
    for (int idx = tid; idx < 256 * 72; idx += TPB) {
        int o = idx / 72, r = idx - o * 72;
        sm[OFF_L1 + idx] = (r < 70) ? L1[o * 70 + r] : 0.f;
    }
    for (int idx = tid; idx < 256 * 12; idx += TPB) {
        int o = idx / 12, j = idx - o * 12;
        sm[OFF_R2 + idx] = (j < 10) ? R2[j * 256 + o] : 0.f;
    }
    for (int idx = tid; idx < 128 * 12; idx += TPB) {
        int o = idx / 12, j = idx - o * 12;
        sm[OFF_L2 + idx] = (j < 10) ? L2[o * 10 + j] : 0.f;
    }
    for (int idx = tid; idx < 128 * 32; idx += TPB) {
        int o = idx / 32, k = idx - o * 32;
        sm[OFF_W3 + idx] = W3[k * 128 + o];
    }
    for (int idx = tid; idx < 32 * 16; idx += TPB) {
        int k = idx / 16, q = idx - k * 16;
        sm[OFF_W4 + idx] = W4[q * 32 + k];
    }
    for (int idx = tid; idx < 16 * 4; idx += TPB) {
        int q = idx / 4, c = idx - q * 4;
        sm[OFF_W5 + idx] = (c < 3) ? W5[c * 16 + q] : 0.f;
    }
    for (int i = tid; i < 256; i += TPB) sm[OFF_B1 + i] = b1[i];
    for (int i = tid; i < 128; i += TPB) sm[OFF_B2 + i] = b2[i];
    for (int i = tid; i < 32;  i += TPB) sm[OFF_B3 + i] = b3[i];
    for (int i = tid; i < 16;  i += TPB) sm[OFF_B4 + i] = b4[i];
    if (tid < 4) sm[OFF_B5 + tid] = (tid < 3) ? b5[tid] : 0.f;
    __syncthreads();

    const float2* bp = reinterpret_cast<const float2*>(&sm[OFF_BP]);
    const int nthreads = gridDim.x * TPB;
    const int stride2  = 2 * nthreads;

    for (int p0 = blockIdx.x * TPB + tid; p0 < npts; p0 += stride2) {
        const int p1  = p0 + nthreads;
        const bool has1 = (p1 < npts);
        const int p1c = has1 ? p1 : p0;     // clamp loads, guard store

        const int ba = p0 >> 12, hwa = p0 & 4095;
        const int bb = p1c >> 12, hwb = p1c & 4095;
        const float c0a = coords[ba * 8192 + hwa];
        const float c1a = coords[ba * 8192 + 4096 + hwa];
        const float c0b = coords[bb * 8192 + hwb];
        const float c1b = coords[bb * 8192 + 4096 + hwb];

        // ==== layer 1 contract: u[70] = x(256) @ R1^T, streamed over GFF dims
        u64 ua[36], ub[36];
        #pragma unroll
        for (int r = 0; r < 36; r++) { ua[r] = 0ull; ub[r] = 0ull; }

        for (int i = 0; i < 128; i++) {
            float2 bv = bp[i];
            float pra = fmaf(c0a, bv.x, c1a * bv.y);
            float prb = fmaf(c0b, bv.x, c1b * bv.y);
            float sa, ca, sb, cb;
            sincosf(pra, &sa, &ca);
            sincosf(prb, &sb, &cb);
            u64 s2a = pack2(sa, sa), c2a = pack2(ca, ca);
            u64 s2b = pack2(sb, sb), c2b = pack2(cb, cb);
            const ulonglong2* rs = reinterpret_cast<const ulonglong2*>(&sm[OFF_RS + i * 72]);
            const ulonglong2* rc = reinterpret_cast<const ulonglong2*>(&sm[OFF_RC + i * 72]);
            #pragma unroll
            for (int r = 0; r < 18; r++) {
                ulonglong2 a = rs[r];
                ulonglong2 d = rc[r];
                ua[2 * r]     = f2fma(s2a, a.x, ua[2 * r]);
                ua[2 * r + 1] = f2fma(s2a, a.y, ua[2 * r + 1]);
                ua[2 * r]     = f2fma(c2a, d.x, ua[2 * r]);
                ua[2 * r + 1] = f2fma(c2a, d.y, ua[2 * r + 1]);
                ub[2 * r]     = f2fma(s2b, a.x, ub[2 * r]);
                ub[2 * r + 1] = f2fma(s2b, a.y, ub[2 * r + 1]);
                ub[2 * r]     = f2fma(c2b, d.x, ub[2 * r]);
                ub[2 * r + 1] = f2fma(c2b, d.y, ub[2 * r + 1]);
            }
        }

        // ==== layer 1 expand + ReLU fused with layer 2 contract
        u64 wa[6], wb[6];
        #pragma unroll
        for (int j = 0; j < 6; j++) { wa[j] = 0ull; wb[j] = 0ull; }

        for (int o = 0; o < 256; o++) {
            const ulonglong2* l1r = reinterpret_cast<const ulonglong2*>(&sm[OFF_L1 + o * 72]);
            u64 aa0 = 0ull, aa1 = 0ull, ab0 = 0ull, ab1 = 0ull;
            #pragma unroll
            for (int r = 0; r < 18; r++) {
                ulonglong2 v = l1r[r];
                aa0 = f2fma(ua[2 * r],     v.x, aa0);
                aa1 = f2fma(ua[2 * r + 1], v.y, aa1);
                ab0 = f2fma(ub[2 * r],     v.x, ab0);
                ab1 = f2fma(ub[2 * r + 1], v.y, ab1);
            }
            float bias1 = sm[OFF_B1 + o];
            float2 ra = unpack2(f2add(aa0, aa1));
            float2 rb = unpack2(f2add(ab0, ab1));
            float ha = fmaxf(ra.x + ra.y + bias1, 0.f);
            float hb = fmaxf(rb.x + rb.y + bias1, 0.f);
            u64 hha = pack2(ha, ha);
            u64 hhb = pack2(hb, hb);
            const ulonglong2* r2r = reinterpret_cast<const ulonglong2*>(&sm[OFF_R2 + o * 12]);
            ulonglong2 q0 = r2r[0], q1 = r2r[1], q2 = r2r[2];
            wa[0] = f2fma(hha, q0.x, wa[0]);
            wa[1] = f2fma(hha, q0.y, wa[1]);
            wa[2] = f2fma(hha, q1.x, wa[2]);
            wa[3] = f2fma(hha, q1.y, wa[3]);
            wa[4] = f2fma(hha, q2.x, wa[4]);
            wa[5] = f2fma(hha, q2.y, wa[5]);
            wb[0] = f2fma(hhb, q0.x, wb[0]);
            wb[1] = f2fma(hhb, q0.y, wb[1]);
            wb[2] = f2fma(hhb, q1.x, wb[2]);
            wb[3] = f2fma(hhb, q1.y, wb[3]);
            wb[4] = f2fma(hhb, q2.x, wb[4]);
            wb[5] = f2fma(hhb, q2.y, wb[5]);
        }

        // ==== layer 2 expand + ReLU fused with layer 3 accumulate
        u64 h3a[16], h3b[16];
        #pragma unroll
        for (int k = 0; k < 16; k++) { h3a[k] = 0ull; h3b[k] = 0ull; }

        for (int o = 0; o < 128; o++) {
            const ulonglong2* l2r = reinterpret_cast<const ulonglong2*>(&sm[OFF_L2 + o * 12]);
            ulonglong2 q0 = l2r[0], q1 = l2r[1], q2 = l2r[2];
            u64 aa = f2fma(wa[0], q0.x, 0ull);
            u64 ab = f2fma(wb[0], q0.x, 0ull);
            aa = f2fma(wa[1], q0.y, aa);  ab = f2fma(wb[1], q0.y, ab);
            aa = f2fma(wa[2], q1.x, aa);  ab = f2fma(wb[2], q1.x, ab);
            aa = f2fma(wa[3], q1.y, aa);  ab = f2fma(wb[3], q1.y, ab);
            aa = f2fma(wa[4], q2.x, aa);  ab = f2fma(wb[4], q2.x, ab);
            aa = f2fma(wa[5], q2.y, aa);  ab = f2fma(wb[5], q2.y, ab);
            float bias2 = sm[OFF_B2 + o];
            float2 va = unpack2(aa);
            float2 vb = unpack2(ab);
            float ha = fmaxf(va.x + va.y + bias2, 0.f);
            float hb = fmaxf(vb.x + vb.y + bias2, 0.f);
            u64 hha = pack2(ha, ha);
            u64 hhb = pack2(hb, hb);
            const ulonglong2* w3r = reinterpret_cast<const ulonglong2*>(&sm[OFF_W3 + o * 32]);
            #pragma unroll
            for (int k = 0; k < 8; k++) {
                ulonglong2 v = w3r[k];
                h3a[2 * k]     = f2fma(hha, v.x, h3a[2 * k]);
                h3a[2 * k + 1] = f2fma(hha, v.y, h3a[2 * k + 1]);
                h3b[2 * k]     = f2fma(hhb, v.x, h3b[2 * k]);
                h3b[2 * k + 1] = f2fma(hhb, v.y, h3b[2 * k + 1]);
            }
        }

        float v3a[32], v3b[32];
        #pragma unroll
        for (int k = 0; k < 16; k++) {
            float b3lo = sm[OFF_B3 + 2 * k], b3hi = sm[OFF_B3 + 2 * k + 1];
            float2 xa = unpack2(h3a[k]);
            float2 xb = unpack2(h3b[k]);
            v3a[2 * k]     = fmaxf(xa.x + b3lo, 0.f);
            v3a[2 * k + 1] = fmaxf(xa.y + b3hi, 0.f);
            v3b[2 * k]     = fmaxf(xb.x + b3lo, 0.f);
            v3b[2 * k + 1] = fmaxf(xb.y + b3hi, 0.f);
        }

        // ==== layer 4: h4[16] = relu(W4 @ h3 + b4)
        u64 h4a[8], h4b[8];
        #pragma unroll
        for (int j = 0; j < 8; j++) { h4a[j] = 0ull; h4b[j] = 0ull; }
        #pragma unroll
        for (int k = 0; k < 32; k++) {
            u64 hha = pack2(v3a[k], v3a[k]);
            u64 hhb = pack2(v3b[k], v3b[k]);
            const ulonglong2* w4r = reinterpret_cast<const ulonglong2*>(&sm[OFF_W4 + k * 16]);
            #pragma unroll
            for (int j = 0; j < 4; j++) {
                ulonglong2 v = w4r[j];
                h4a[2 * j]     = f2fma(hha, v.x, h4a[2 * j]);
                h4a[2 * j + 1] = f2fma(hha, v.y, h4a[2 * j + 1]);
                h4b[2 * j]     = f2fma(hhb, v.x, h4b[2 * j]);
                h4b[2 * j + 1] = f2fma(hhb, v.y, h4b[2 * j + 1]);
            }
        }
        float v4a[16], v4b[16];
        #pragma unroll
        for (int j = 0; j < 8; j++) {
            float b4lo = sm[OFF_B4 + 2 * j], b4hi = sm[OFF_B4 + 2 * j + 1];
            float2 xa = unpack2(h4a[j]);
            float2 xb = unpack2(h4b[j]);
            v4a[2 * j]     = fmaxf(xa.x + b4lo, 0.f);
            v4a[2 * j + 1] = fmaxf(xa.y + b4hi, 0.f);
            v4b[2 * j]     = fmaxf(xb.x + b4lo, 0.f);
            v4b[2 * j + 1] = fmaxf(xb.y + b4hi, 0.f);
        }

        // ==== layer 5: out[3] = W5 @ h4 + b5
        u64 oa0 = 0ull, oa1 = 0ull, ob0 = 0ull, ob1 = 0ull;
        #pragma unroll
        for (int q = 0; q < 16; q++) {
            u64 hha = pack2(v4a[q], v4a[q]);
            u64 hhb = pack2(v4b[q], v4b[q]);
            const ulonglong2* w5r = reinterpret_cast<const ulonglong2*>(&sm[OFF_W5 + q * 4]);
            ulonglong2 v = w5r[0];
            oa0 = f2fma(hha, v.x, oa0);
            oa1 = f2fma(hha, v.y, oa1);
            ob0 = f2fma(hhb, v.x, ob0);
            ob1 = f2fma(hhb, v.y, ob1);
        }
        float bz0 = sm[OFF_B5 + 0], bz1 = sm[OFF_B5 + 1], bz2 = sm[OFF_B5 + 2];
        {
            float2 xa = unpack2(oa0);
            float2 ya = unpack2(oa1);
            out[3 * p0 + 0] = xa.x + bz0;
            out[3 * p0 + 1] = xa.y + bz1;
            out[3 * p0 + 2] = ya.x + bz2;
        }
        if (has1) {
            float2 xb = unpack2(ob0);
            float2 yb = unpack2(ob1);
            out[3 * p1 + 0] = xb.x + bz0;
            out[3 * p1 + 1] = xb.y + bz1;
            out[3 * p1 + 2] = yb.x + bz2;
        }
    }
}

extern "C" void kernel_launch(void* const* d_in, const int* in_sizes, int n_in,
                              void* d_out, int out_size) {
    const float* coords = (const float*)d_in[0];
    const float* Bmat   = (const float*)d_in[1];
    const float* L1     = (const float*)d_in[2];
    const float* R1     = (const float*)d_in[3];
    const float* b1     = (const float*)d_in[4];
    const float* L2     = (const float*)d_in[5];
    const float* R2     = (const float*)d_in[6];
    const float* b2     = (const float*)d_in[7];
    const float* W3     = (const float*)d_in[8];
    const float* b3     = (const float*)d_in[9];
    const float* W4     = (const float*)d_in[10];
    const float* b4     = (const float*)d_in[11];
    const float* W5     = (const float*)d_in[12];
    const float* b5     = (const float*)d_in[13];
    float* out = (float*)d_out;

    const int npts = in_sizes[0] / 2;  // coords is [B,2,H,W]

    int dev = 0;
    cudaGetDevice(&dev);
    int sms = 148;
    cudaDeviceGetAttribute(&sms, cudaDevAttrMultiProcessorCount, dev);

    const size_t smem_bytes = SMEM_FLOATS * sizeof(float);
    cudaFuncSetAttribute(implicit_mlp_kernel,
                         cudaFuncAttributeMaxDynamicSharedMemorySize,
                         (int)smem_bytes);

    implicit_mlp_kernel<<<sms, TPB, smem_bytes>>>(
        coords, Bmat, L1, R1, b1, L2, R2, b2, W3, b3, W4, b4, W5, b5,
        out, npts);
}

// round 4
// speedup vs baseline: 1.0744x; 1.0744x over previous
#include <cuda_runtime.h>
#include <math.h>

// ============================================================================
// ImplicitMLP: GFF(128) -> FMM(256->256,r=70) -> FMM(256->128,r=10)
//              -> 128->32 -> 32->16 -> 16->3, fp32, ReLU between layers.
// TWO points per thread (weight LDS amortized across both). TPB=320 with
// launch_bounds(320,1): 204-reg cap fits the ~190-reg live set (round-3's
// 168-reg cap spilled), giving 10 warps/SM for latency hiding.
// __sincosf (fast path): fewer temps + fewer issue slots; error budget huge.
// Packed f32x2 FMA throughout. Weights staged transposed/padded in smem.
// ============================================================================

#define TPB 320

typedef unsigned long long u64;

__device__ __forceinline__ u64 f2fma(u64 a, u64 b, u64 c) {
    u64 d;
    asm("fma.rn.f32x2 %0, %1, %2, %3;" : "=l"(d) : "l"(a), "l"(b), "l"(c));
    return d;
}
__device__ __forceinline__ u64 f2add(u64 a, u64 b) {
    u64 d;
    asm("add.rn.f32x2 %0, %1, %2;" : "=l"(d) : "l"(a), "l"(b));
    return d;
}
__device__ __forceinline__ u64 pack2(float lo, float hi) {
    u64 r;
    asm("mov.b64 %0, {%1, %2};" : "=l"(r) : "f"(lo), "f"(hi));
    return r;
}
__device__ __forceinline__ float2 unpack2(u64 v) {
    float lo, hi;
    asm("mov.b64 {%0, %1}, %2;" : "=f"(lo), "=f"(hi) : "l"(v));
    return make_float2(lo, hi);
}

// ---- shared memory layout (float offsets) ----
#define OFF_BP 0
#define OFF_RS 256
#define OFF_RC 9472
#define OFF_L1 18688
#define OFF_R2 37120
#define OFF_L2 40192
#define OFF_W3 41728
#define OFF_W4 45824
#define OFF_W5 46336
#define OFF_B1 46400
#define OFF_B2 46656
#define OFF_B3 46784
#define OFF_B4 46816
#define OFF_B5 46832
#define SMEM_FLOATS 46840

__global__ void __launch_bounds__(TPB, 1) implicit_mlp_kernel(
    const float* __restrict__ coords, const float* __restrict__ Bmat,
    const float* __restrict__ L1, const float* __restrict__ R1, const float* __restrict__ b1,
    const float* __restrict__ L2, const float* __restrict__ R2, const float* __restrict__ b2,
    const float* __restrict__ W3, const float* __restrict__ b3,
    const float* __restrict__ W4, const float* __restrict__ b4,
    const float* __restrict__ W5, const float* __restrict__ b5,
    float* __restrict__ out, int npts)
{
    extern __shared__ float sm[];
    const int tid = threadIdx.x;
    const float TWOPI = 6.283185307179586f;

    // ---- stage transposed/padded weights into smem ----
    for (int i = tid; i < 128; i += TPB) {
        sm[OFF_BP + 2 * i]     = Bmat[i] * TWOPI;
        sm[OFF_BP + 2 * i + 1] = Bmat[128 + i] * TWOPI;
    }
    for (int idx = tid; idx < 128 * 72; idx += TPB) {
        int i = idx / 72, r = idx - i * 72;
        float vs = 0.f, vc = 0.f;
        if (r < 70) { vs = R1[r * 256 + i]; vc = R1[r * 256 + 128 + i]; }
        sm[OFF_RS + idx] = vs;
        sm[OFF_RC + idx] = vc;
    }
    for (int idx = tid; idx < 256 * 72; idx += TPB) {
        int o = idx / 72, r = idx - o * 72;
        sm[OFF_L1 + idx] = (r < 70) ? L1[o * 70 + r] : 0.f;
    }
    for (int idx = tid; idx < 256 * 12; idx += TPB) {
        int o = idx / 12, j = idx - o * 12;
        sm[OFF_R2 + idx] = (j < 10) ? R2[j * 256 + o] : 0.f;
    }
    for (int idx = tid; idx < 128 * 12; idx += TPB) {
        int o = idx / 12, j = idx - o * 12;
        sm[OFF_L2 + idx] = (j < 10) ? L2[o * 10 + j] : 0.f;
    }
    for (int idx = tid; idx < 128 * 32; idx += TPB) {
        int o = idx / 32, k = idx - o * 32;
        sm[OFF_W3 + idx] = W3[k * 128 + o];
    }
    for (int idx = tid; idx < 32 * 16; idx += TPB) {
        int k = idx / 16, q = idx - k * 16;
        sm[OFF_W4 + idx] = W4[q * 32 + k];
    }
    for (int idx = tid; idx < 16 * 4; idx += TPB) {
        int q = idx / 4, c = idx - q * 4;
        sm[OFF_W5 + idx] = (c < 3) ? W5[c * 16 + q] : 0.f;
    }
    for (int i = tid; i < 256; i += TPB) sm[OFF_B1 + i] = b1[i];
    for (int i = tid; i < 128; i += TPB) sm[OFF_B2 + i] = b2[i];
    for (int i = tid; i < 32;  i += TPB) sm[OFF_B3 + i] = b3[i];
    for (int i = tid; i < 16;  i += TPB) sm[OFF_B4 + i] = b4[i];
    if (tid < 4) sm[OFF_B5 + tid] = (tid < 3) ? b5[tid] : 0.f;
    __syncthreads();

    const float2* bp = reinterpret_cast<const float2*>(&sm[OFF_BP]);
    const int nthreads = gridDim.x * TPB;
    const int stride2  = 2 * nthreads;

    for (int p0 = blockIdx.x * TPB + tid; p0 < npts; p0 += stride2) {
        const int p1  = p0 + nthreads;
        const bool has1 = (p1 < npts);
        const int p1c = has1 ? p1 : p0;     // clamp loads, guard store

        const int ba = p0 >> 12, hwa = p0 & 4095;
        const int bb = p1c >> 12, hwb = p1c & 4095;
        const float c0a = coords[ba * 8192 + hwa];
        const float c1a = coords[ba * 8192 + 4096 + hwa];
        const float c0b = coords[bb * 8192 + hwb];
        const float c1b = coords[bb * 8192 + 4096 + hwb];

        // ==== layer 1 contract: u[70] = x(256) @ R1^T, streamed over GFF dims
        u64 ua[36], ub[36];
        #pragma unroll
        for (int r = 0; r < 36; r++) { ua[r] = 0ull; ub[r] = 0ull; }

        for (int i = 0; i < 128; i++) {
            float2 bv = bp[i];
            float pra = fmaf(c0a, bv.x, c1a * bv.y);
            float prb = fmaf(c0b, bv.x, c1b * bv.y);
            float sa, ca, sb, cb;
            __sincosf(pra, &sa, &ca);
            __sincosf(prb, &sb, &cb);
            u64 s2a = pack2(sa, sa), c2a = pack2(ca, ca);
            u64 s2b = pack2(sb, sb), c2b = pack2(cb, cb);
            const ulonglong2* rs = reinterpret_cast<const ulonglong2*>(&sm[OFF_RS + i * 72]);
            const ulonglong2* rc = reinterpret_cast<const ulonglong2*>(&sm[OFF_RC + i * 72]);
            #pragma unroll
            for (int r = 0; r < 18; r++) {
                ulonglong2 a = rs[r];
                ulonglong2 d = rc[r];
                ua[2 * r]     = f2fma(s2a, a.x, ua[2 * r]);
                ua[2 * r + 1] = f2fma(s2a, a.y, ua[2 * r + 1]);
                ua[2 * r]     = f2fma(c2a, d.x, ua[2 * r]);
                ua[2 * r + 1] = f2fma(c2a, d.y, ua[2 * r + 1]);
                ub[2 * r]     = f2fma(s2b, a.x, ub[2 * r]);
                ub[2 * r + 1] = f2fma(s2b, a.y, ub[2 * r + 1]);
                ub[2 * r]     = f2fma(c2b, d.x, ub[2 * r]);
                ub[2 * r + 1] = f2fma(c2b, d.y, ub[2 * r + 1]);
            }
        }

        // ==== layer 1 expand + ReLU fused with layer 2 contract
        u64 wa[6], wb[6];
        #pragma unroll
        for (int j = 0; j < 6; j++) { wa[j] = 0ull; wb[j] = 0ull; }

        for (int o = 0; o < 256; o++) {
            const ulonglong2* l1r = reinterpret_cast<const ulonglong2*>(&sm[OFF_L1 + o * 72]);
            u64 aa0 = 0ull, aa1 = 0ull, ab0 = 0ull, ab1 = 0ull;
            #pragma unroll
            for (int r = 0; r < 18; r++) {
                ulonglong2 v = l1r[r];
                aa0 = f2fma(ua[2 * r],     v.x, aa0);
                aa1 = f2fma(ua[2 * r + 1], v.y, aa1);
                ab0 = f2fma(ub[2 * r],     v.x, ab0);
                ab1 = f2fma(ub[2 * r + 1], v.y, ab1);
            }
            float bias1 = sm[OFF_B1 + o];
            float2 ra = unpack2(f2add(aa0, aa1));
            float2 rb = unpack2(f2add(ab0, ab1));
            float ha = fmaxf(ra.x + ra.y + bias1, 0.f);
            float hb = fmaxf(rb.x + rb.y + bias1, 0.f);
            u64 hha = pack2(ha, ha);
            u64 hhb = pack2(hb, hb);
            const ulonglong2* r2r = reinterpret_cast<const ulonglong2*>(&sm[OFF_R2 + o * 12]);
            ulonglong2 q0 = r2r[0], q1 = r2r[1], q2 = r2r[2];
            wa[0] = f2fma(hha, q0.x, wa[0]);
            wa[1] = f2fma(hha, q0.y, wa[1]);
            wa[2] = f2fma(hha, q1.x, wa[2]);
            wa[3] = f2fma(hha, q1.y, wa[3]);
            wa[4] = f2fma(hha, q2.x, wa[4]);
            wa[5] = f2fma(hha, q2.y, wa[5]);
            wb[0] = f2fma(hhb, q0.x, wb[0]);
            wb[1] = f2fma(hhb, q0.y, wb[1]);
            wb[2] = f2fma(hhb, q1.x, wb[2]);
            wb[3] = f2fma(hhb, q1.y, wb[3]);
            wb[4] = f2fma(hhb, q2.x, wb[4]);
            wb[5] = f2fma(hhb, q2.y, wb[5]);
        }

        // ==== layer 2 expand + ReLU fused with layer 3 accumulate
        u64 h3a[16], h3b[16];
        #pragma unroll
        for (int k = 0; k < 16; k++) { h3a[k] = 0ull; h3b[k] = 0ull; }

        for (int o = 0; o < 128; o++) {
            const ulonglong2* l2r = reinterpret_cast<const ulonglong2*>(&sm[OFF_L2 + o * 12]);
            ulonglong2 q0 = l2r[0], q1 = l2r[1], q2 = l2r[2];
            u64 aa = f2fma(wa[0], q0.x, 0ull);
            u64 ab = f2fma(wb[0], q0.x, 0ull);
            aa = f2fma(wa[1], q0.y, aa);  ab = f2fma(wb[1], q0.y, ab);
            aa = f2fma(wa[2], q1.x, aa);  ab = f2fma(wb[2], q1.x, ab);
            aa = f2fma(wa[3], q1.y, aa);  ab = f2fma(wb[3], q1.y, ab);
            aa = f2fma(wa[4], q2.x, aa);  ab = f2fma(wb[4], q2.x, ab);
            aa = f2fma(wa[5], q2.y, aa);  ab = f2fma(wb[5], q2.y, ab);
            float bias2 = sm[OFF_B2 + o];
            float2 va = unpack2(aa);
            float2 vb = unpack2(ab);
            float ha = fmaxf(va.x + va.y + bias2, 0.f);
            float hb = fmaxf(vb.x + vb.y + bias2, 0.f);
            u64 hha = pack2(ha, ha);
            u64 hhb = pack2(hb, hb);
            const ulonglong2* w3r = reinterpret_cast<const ulonglong2*>(&sm[OFF_W3 + o * 32]);
            #pragma unroll
            for (int k = 0; k < 8; k++) {
                ulonglong2 v = w3r[k];
                h3a[2 * k]     = f2fma(hha, v.x, h3a[2 * k]);
                h3a[2 * k + 1] = f2fma(hha, v.y, h3a[2 * k + 1]);
                h3b[2 * k]     = f2fma(hhb, v.x, h3b[2 * k]);
                h3b[2 * k + 1] = f2fma(hhb, v.y, h3b[2 * k + 1]);
            }
        }

        float v3a[32], v3b[32];
        #pragma unroll
        for (int k = 0; k < 16; k++) {
            float b3lo = sm[OFF_B3 + 2 * k], b3hi = sm[OFF_B3 + 2 * k + 1];
            float2 xa = unpack2(h3a[k]);
            float2 xb = unpack2(h3b[k]);
            v3a[2 * k]     = fmaxf(xa.x + b3lo, 0.f);
            v3a[2 * k + 1] = fmaxf(xa.y + b3hi, 0.f);
            v3b[2 * k]     = fmaxf(xb.x + b3lo, 0.f);
            v3b[2 * k + 1] = fmaxf(xb.y + b3hi, 0.f);
        }

        // ==== layer 4: h4[16] = relu(W4 @ h3 + b4)
        u64 h4a[8], h4b[8];
        #pragma unroll
        for (int j = 0; j < 8; j++) { h4a[j] = 0ull; h4b[j] = 0ull; }
        #pragma unroll
        for (int k = 0; k < 32; k++) {
            u64 hha = pack2(v3a[k], v3a[k]);
            u64 hhb = pack2(v3b[k], v3b[k]);
            const ulonglong2* w4r = reinterpret_cast<const ulonglong2*>(&sm[OFF_W4 + k * 16]);
            #pragma unroll
            for (int j = 0; j < 4; j++) {
                ulonglong2 v = w4r[j];
                h4a[2 * j]     = f2fma(hha, v.x, h4a[2 * j]);
                h4a[2 * j + 1] = f2fma(hha, v.y, h4a[2 * j + 1]);
                h4b[2 * j]     = f2fma(hhb, v.x, h4b[2 * j]);
                h4b[2 * j + 1] = f2fma(hhb, v.y, h4b[2 * j + 1]);
            }
        }
        float v4a[16], v4b[16];
        #pragma unroll
        for (int j = 0; j < 8; j++) {
            float b4lo = sm[OFF_B4 + 2 * j], b4hi = sm[OFF_B4 + 2 * j + 1];
            float2 xa = unpack2(h4a[j]);
            float2 xb = unpack2(h4b[j]);
            v4a[2 * j]     = fmaxf(xa.x + b4lo, 0.f);
            v4a[2 * j + 1] = fmaxf(xa.y + b4hi, 0.f);
            v4b[2 * j]     = fmaxf(xb.x + b4lo, 0.f);
            v4b[2 * j + 1] = fmaxf(xb.y + b4hi, 0.f);
        }

        // ==== layer 5: out[3] = W5 @ h4 + b5
        u64 oa0 = 0ull, oa1 = 0ull, ob0 = 0ull, ob1 = 0ull;
        #pragma unroll
        for (int q = 0; q < 16; q++) {
            u64 hha = pack2(v4a[q], v4a[q]);
            u64 hhb = pack2(v4b[q], v4b[q]);
            const ulonglong2* w5r = reinterpret_cast<const ulonglong2*>(&sm[OFF_W5 + q * 4]);
            ulonglong2 v = w5r[0];
            oa0 = f2fma(hha, v.x, oa0);
            oa1 = f2fma(hha, v.y, oa1);
            ob0 = f2fma(hhb, v.x, ob0);
            ob1 = f2fma(hhb, v.y, ob1);
        }
        float bz0 = sm[OFF_B5 + 0], bz1 = sm[OFF_B5 + 1], bz2 = sm[OFF_B5 + 2];
        {
            float2 xa = unpack2(oa0);
            float2 ya = unpack2(oa1);
            out[3 * p0 + 0] = xa.x + bz0;
            out[3 * p0 + 1] = xa.y + bz1;
            out[3 * p0 + 2] = ya.x + bz2;
        }
        if (has1) {
            float2 xb = unpack2(ob0);
            float2 yb = unpack2(ob1);
            out[3 * p1 + 0] = xb.x + bz0;
            out[3 * p1 + 1] = xb.y + bz1;
            out[3 * p1 + 2] = yb.x + bz2;
        }
    }
}

extern "C" void kernel_launch(void* const* d_in, const int* in_sizes, int n_in,
                              void* d_out, int out_size) {
    const float* coords = (const float*)d_in[0];
    const float* Bmat   = (const float*)d_in[1];
    const float* L1     = (const float*)d_in[2];
    const float* R1     = (const float*)d_in[3];
    const float* b1     = (const float*)d_in[4];
    const float* L2     = (const float*)d_in[5];
    const float* R2     = (const float*)d_in[6];
    const float* b2     = (const float*)d_in[7];
    const float* W3     = (const float*)d_in[8];
    const float* b3     = (const float*)d_in[9];
    const float* W4     = (const float*)d_in[10];
    const float* b4     = (const float*)d_in[11];
    const float* W5     = (const float*)d_in[12];
    const float* b5     = (const float*)d_in[13];
    float* out = (float*)d_out;

    const int npts = in_sizes[0] / 2;  // coords is [B,2,H,W]

    int dev = 0;
    cudaGetDevice(&dev);
    int sms = 148;
    cudaDeviceGetAttribute(&sms, cudaDevAttrMultiProcessorCount, dev);

    const size_t smem_bytes = SMEM_FLOATS * sizeof(float);
    cudaFuncSetAttribute(implicit_mlp_kernel,
                         cudaFuncAttributeMaxDynamicSharedMemorySize,
                         (int)smem_bytes);

    implicit_mlp_kernel<<<sms, TPB, smem_bytes>>>(
        coords, Bmat, L1, R1, b1, L2, R2, b2, W3, b3, W4, b4, W5, b5,
        out, npts);
}

// round 5
// speedup vs baseline: 2.0511x; 1.9090x over previous
#include <cuda_runtime.h>
#include <math.h>

// ============================================================================
// ImplicitMLP: GFF(128) -> FMM(256->256,r=70) -> FMM(256->128,r=10)
//              -> 128->32 -> 32->16 -> 16->3, fp32, ReLU between layers.
// TWO points per thread (weight LDS amortized across both). TPB=256 with
// launch_bounds(256,1): the only config where the ~190-reg live set fits
// without spilling (rounds 3/4 proved ptxas caps at 168 for TPB>=320 and
// spills). __sincosf fast path: removes the accurate range-reduction
// instruction stream (~23% of issue slots) and frees ~12 regs of temps.
// Packed f32x2 FMA throughout. Weights staged transposed/padded in smem.
// ============================================================================

#define TPB 256

typedef unsigned long long u64;

__device__ __forceinline__ u64 f2fma(u64 a, u64 b, u64 c) {
    u64 d;
    asm("fma.rn.f32x2 %0, %1, %2, %3;" : "=l"(d) : "l"(a), "l"(b), "l"(c));
    return d;
}
__device__ __forceinline__ u64 f2add(u64 a, u64 b) {
    u64 d;
    asm("add.rn.f32x2 %0, %1, %2;" : "=l"(d) : "l"(a), "l"(b));
    return d;
}
__device__ __forceinline__ u64 pack2(float lo, float hi) {
    u64 r;
    asm("mov.b64 %0, {%1, %2};" : "=l"(r) : "f"(lo), "f"(hi));
    return r;
}
__device__ __forceinline__ float2 unpack2(u64 v) {
    float lo, hi;
    asm("mov.b64 {%0, %1}, %2;" : "=f"(lo), "=f"(hi) : "l"(v));
    return make_float2(lo, hi);
}

// ---- shared memory layout (float offsets) ----
#define OFF_BP 0
#define OFF_RS 256
#define OFF_RC 9472
#define OFF_L1 18688
#define OFF_R2 37120
#define OFF_L2 40192
#define OFF_W3 41728
#define OFF_W4 45824
#define OFF_W5 46336
#define OFF_B1 46400
#define OFF_B2 46656
#define OFF_B3 46784
#define OFF_B4 46816
#define OFF_B5 46832
#define SMEM_FLOATS 46840

__global__ void __launch_bounds__(TPB, 1) implicit_mlp_kernel(
    const float* __restrict__ coords, const float* __restrict__ Bmat,
    const float* __restrict__ L1, const float* __restrict__ R1, const float* __restrict__ b1,
    const float* __restrict__ L2, const float* __restrict__ R2, const float* __restrict__ b2,
    const float* __restrict__ W3, const float* __restrict__ b3,
    const float* __restrict__ W4, const float* __restrict__ b4,
    const float* __restrict__ W5, const float* __restrict__ b5,
    float* __restrict__ out, int npts)
{
    extern __shared__ float sm[];
    const int tid = threadIdx.x;
    const float TWOPI = 6.283185307179586f;

    // ---- stage transposed/padded weights into smem ----
    for (int i = tid; i < 128; i += TPB) {
        sm[OFF_BP + 2 * i]     = Bmat[i] * TWOPI;
        sm[OFF_BP + 2 * i + 1] = Bmat[128 + i] * TWOPI;
    }
    for (int idx = tid; idx < 128 * 72; idx += TPB) {
        int i = idx / 72, r = idx - i * 72;
        float vs = 0.f, vc = 0.f;
        if (r < 70) { vs = R1[r * 256 + i]; vc = R1[r * 256 + 128 + i]; }
        sm[OFF_RS + idx] = vs;
        sm[OFF_RC + idx] = vc;
    }
    for (int idx = tid; idx < 256 * 72; idx += TPB) {
        int o = idx / 72, r = idx - o * 72;
        sm[OFF_L1 + idx] = (r < 70) ? L1[o * 70 + r] : 0.f;
    }
    for (int idx = tid; idx < 256 * 12; idx += TPB) {
        int o = idx / 12, j = idx - o * 12;
        sm[OFF_R2 + idx] = (j < 10) ? R2[j * 256 + o] : 0.f;
    }
    for (int idx = tid; idx < 128 * 12; idx += TPB) {
        int o = idx / 12, j = idx - o * 12;
        sm[OFF_L2 + idx] = (j < 10) ? L2[o * 10 + j] : 0.f;
    }
    for (int idx = tid; idx < 128 * 32; idx += TPB) {
        int o = idx / 32, k = idx - o * 32;
        sm[OFF_W3 + idx] = W3[k * 128 + o];
    }
    for (int idx = tid; idx < 32 * 16; idx += TPB) {
        int k = idx / 16, q = idx - k * 16;
        sm[OFF_W4 + idx] = W4[q * 32 + k];
    }
    for (int idx = tid; idx < 16 * 4; idx += TPB) {
        int q = idx / 4, c = idx - q * 4;
        sm[OFF_W5 + idx] = (c < 3) ? W5[c * 16 + q] : 0.f;
    }
    for (int i = tid; i < 256; i += TPB) sm[OFF_B1 + i] = b1[i];
    for (int i = tid; i < 128; i += TPB) sm[OFF_B2 + i] = b2[i];
    for (int i = tid; i < 32;  i += TPB) sm[OFF_B3 + i] = b3[i];
    for (int i = tid; i < 16;  i += TPB) sm[OFF_B4 + i] = b4[i];
    if (tid < 4) sm[OFF_B5 + tid] = (tid < 3) ? b5[tid] : 0.f;
    __syncthreads();

    const float2* bp = reinterpret_cast<const float2*>(&sm[OFF_BP]);
    const int nthreads = gridDim.x * TPB;
    const int stride2  = 2 * nthreads;

    for (int p0 = blockIdx.x * TPB + tid; p0 < npts; p0 += stride2) {
        const int p1  = p0 + nthreads;
        const bool has1 = (p1 < npts);
        const int p1c = has1 ? p1 : p0;     // clamp loads, guard store

        const int ba = p0 >> 12, hwa = p0 & 4095;
        const int bb = p1c >> 12, hwb = p1c & 4095;
        const float c0a = coords[ba * 8192 + hwa];
        const float c1a = coords[ba * 8192 + 4096 + hwa];
        const float c0b = coords[bb * 8192 + hwb];
        const float c1b = coords[bb * 8192 + 4096 + hwb];

        // ==== layer 1 contract: u[70] = x(256) @ R1^T, streamed over GFF dims
        u64 ua[36], ub[36];
        #pragma unroll
        for (int r = 0; r < 36; r++) { ua[r] = 0ull; ub[r] = 0ull; }

        for (int i = 0; i < 128; i++) {
            float2 bv = bp[i];
            float pra = fmaf(c0a, bv.x, c1a * bv.y);
            float prb = fmaf(c0b, bv.x, c1b * bv.y);
            float sa, ca, sb, cb;
            __sincosf(pra, &sa, &ca);
            __sincosf(prb, &sb, &cb);
            u64 s2a = pack2(sa, sa), c2a = pack2(ca, ca);
            u64 s2b = pack2(sb, sb), c2b = pack2(cb, cb);
            const ulonglong2* rs = reinterpret_cast<const ulonglong2*>(&sm[OFF_RS + i * 72]);
            const ulonglong2* rc = reinterpret_cast<const ulonglong2*>(&sm[OFF_RC + i * 72]);
            #pragma unroll
            for (int r = 0; r < 18; r++) {
                ulonglong2 a = rs[r];
                ulonglong2 d = rc[r];
                ua[2 * r]     = f2fma(s2a, a.x, ua[2 * r]);
                ua[2 * r + 1] = f2fma(s2a, a.y, ua[2 * r + 1]);
                ua[2 * r]     = f2fma(c2a, d.x, ua[2 * r]);
                ua[2 * r + 1] = f2fma(c2a, d.y, ua[2 * r + 1]);
                ub[2 * r]     = f2fma(s2b, a.x, ub[2 * r]);
                ub[2 * r + 1] = f2fma(s2b, a.y, ub[2 * r + 1]);
                ub[2 * r]     = f2fma(c2b, d.x, ub[2 * r]);
                ub[2 * r + 1] = f2fma(c2b, d.y, ub[2 * r + 1]);
            }
        }

        // ==== layer 1 expand + ReLU fused with layer 2 contract
        u64 wa[6], wb[6];
        #pragma unroll
        for (int j = 0; j < 6; j++) { wa[j] = 0ull; wb[j] = 0ull; }

        for (int o = 0; o < 256; o++) {
            const ulonglong2* l1r = reinterpret_cast<const ulonglong2*>(&sm[OFF_L1 + o * 72]);
            u64 aa0 = 0ull, aa1 = 0ull, ab0 = 0ull, ab1 = 0ull;
            #pragma unroll
            for (int r = 0; r < 18; r++) {
                ulonglong2 v = l1r[r];
                aa0 = f2fma(ua[2 * r],     v.x, aa0);
                aa1 = f2fma(ua[2 * r + 1], v.y, aa1);
                ab0 = f2fma(ub[2 * r],     v.x, ab0);
                ab1 = f2fma(ub[2 * r + 1], v.y, ab1);
            }
            float bias1 = sm[OFF_B1 + o];
            float2 ra = unpack2(f2add(aa0, aa1));
            float2 rb = unpack2(f2add(ab0, ab1));
            float ha = fmaxf(ra.x + ra.y + bias1, 0.f);
            float hb = fmaxf(rb.x + rb.y + bias1, 0.f);
            u64 hha = pack2(ha, ha);
            u64 hhb = pack2(hb, hb);
            const ulonglong2* r2r = reinterpret_cast<const ulonglong2*>(&sm[OFF_R2 + o * 12]);
            ulonglong2 q0 = r2r[0], q1 = r2r[1], q2 = r2r[2];
            wa[0] = f2fma(hha, q0.x, wa[0]);
            wa[1] = f2fma(hha, q0.y, wa[1]);
            wa[2] = f2fma(hha, q1.x, wa[2]);
            wa[3] = f2fma(hha, q1.y, wa[3]);
            wa[4] = f2fma(hha, q2.x, wa[4]);
            wa[5] = f2fma(hha, q2.y, wa[5]);
            wb[0] = f2fma(hhb, q0.x, wb[0]);
            wb[1] = f2fma(hhb, q0.y, wb[1]);
            wb[2] = f2fma(hhb, q1.x, wb[2]);
            wb[3] = f2fma(hhb, q1.y, wb[3]);
            wb[4] = f2fma(hhb, q2.x, wb[4]);
            wb[5] = f2fma(hhb, q2.y, wb[5]);
        }

        // ==== layer 2 expand + ReLU fused with layer 3 accumulate
        u64 h3a[16], h3b[16];
        #pragma unroll
        for (int k = 0; k < 16; k++) { h3a[k] = 0ull; h3b[k] = 0ull; }

        for (int o = 0; o < 128; o++) {
            const ulonglong2* l2r = reinterpret_cast<const ulonglong2*>(&sm[OFF_L2 + o * 12]);
            ulonglong2 q0 = l2r[0], q1 = l2r[1], q2 = l2r[2];
            u64 aa = f2fma(wa[0], q0.x, 0ull);
            u64 ab = f2fma(wb[0], q0.x, 0ull);
            aa = f2fma(wa[1], q0.y, aa);  ab = f2fma(wb[1], q0.y, ab);
            aa = f2fma(wa[2], q1.x, aa);  ab = f2fma(wb[2], q1.x, ab);
            aa = f2fma(wa[3], q1.y, aa);  ab = f2fma(wb[3], q1.y, ab);
            aa = f2fma(wa[4], q2.x, aa);  ab = f2fma(wb[4], q2.x, ab);
            aa = f2fma(wa[5], q2.y, aa);  ab = f2fma(wb[5], q2.y, ab);
            float bias2 = sm[OFF_B2 + o];
            float2 va = unpack2(aa);
            float2 vb = unpack2(ab);
            float ha = fmaxf(va.x + va.y + bias2, 0.f);
            float hb = fmaxf(vb.x + vb.y + bias2, 0.f);
            u64 hha = pack2(ha, ha);
            u64 hhb = pack2(hb, hb);
            const ulonglong2* w3r = reinterpret_cast<const ulonglong2*>(&sm[OFF_W3 + o * 32]);
            #pragma unroll
            for (int k = 0; k < 8; k++) {
                ulonglong2 v = w3r[k];
                h3a[2 * k]     = f2fma(hha, v.x, h3a[2 * k]);
                h3a[2 * k + 1] = f2fma(hha, v.y, h3a[2 * k + 1]);
                h3b[2 * k]     = f2fma(hhb, v.x, h3b[2 * k]);
                h3b[2 * k + 1] = f2fma(hhb, v.y, h3b[2 * k + 1]);
            }
        }

        float v3a[32], v3b[32];
        #pragma unroll
        for (int k = 0; k < 16; k++) {
            float b3lo = sm[OFF_B3 + 2 * k], b3hi = sm[OFF_B3 + 2 * k + 1];
            float2 xa = unpack2(h3a[k]);
            float2 xb = unpack2(h3b[k]);
            v3a[2 * k]     = fmaxf(xa.x + b3lo, 0.f);
            v3a[2 * k + 1] = fmaxf(xa.y + b3hi, 0.f);
            v3b[2 * k]     = fmaxf(xb.x + b3lo, 0.f);
            v3b[2 * k + 1] = fmaxf(xb.y + b3hi, 0.f);
        }

        // ==== layer 4: h4[16] = relu(W4 @ h3 + b4)
        u64 h4a[8], h4b[8];
        #pragma unroll
        for (int j = 0; j < 8; j++) { h4a[j] = 0ull; h4b[j] = 0ull; }
        #pragma unroll
        for (int k = 0; k < 32; k++) {
            u64 hha = pack2(v3a[k], v3a[k]);
            u64 hhb = pack2(v3b[k], v3b[k]);
            const ulonglong2* w4r = reinterpret_cast<const ulonglong2*>(&sm[OFF_W4 + k * 16]);
            #pragma unroll
            for (int j = 0; j < 4; j++) {
                ulonglong2 v = w4r[j];
                h4a[2 * j]     = f2fma(hha, v.x, h4a[2 * j]);
                h4a[2 * j + 1] = f2fma(hha, v.y, h4a[2 * j + 1]);
                h4b[2 * j]     = f2fma(hhb, v.x, h4b[2 * j]);
                h4b[2 * j + 1] = f2fma(hhb, v.y, h4b[2 * j + 1]);
            }
        }
        float v4a[16], v4b[16];
        #pragma unroll
        for (int j = 0; j < 8; j++) {
            float b4lo = sm[OFF_B4 + 2 * j], b4hi = sm[OFF_B4 + 2 * j + 1];
            float2 xa = unpack2(h4a[j]);
            float2 xb = unpack2(h4b[j]);
            v4a[2 * j]     = fmaxf(xa.x + b4lo, 0.f);
            v4a[2 * j + 1] = fmaxf(xa.y + b4hi, 0.f);
            v4b[2 * j]     = fmaxf(xb.x + b4lo, 0.f);
            v4b[2 * j + 1] = fmaxf(xb.y + b4hi, 0.f);
        }

        // ==== layer 5: out[3] = W5 @ h4 + b5
        u64 oa0 = 0ull, oa1 = 0ull, ob0 = 0ull, ob1 = 0ull;
        #pragma unroll
        for (int q = 0; q < 16; q++) {
            u64 hha = pack2(v4a[q], v4a[q]);
            u64 hhb = pack2(v4b[q], v4b[q]);
            const ulonglong2* w5r = reinterpret_cast<const ulonglong2*>(&sm[OFF_W5 + q * 4]);
            ulonglong2 v = w5r[0];
            oa0 = f2fma(hha, v.x, oa0);
            oa1 = f2fma(hha, v.y, oa1);
            ob0 = f2fma(hhb, v.x, ob0);
            ob1 = f2fma(hhb, v.y, ob1);
        }
        float bz0 = sm[OFF_B5 + 0], bz1 = sm[OFF_B5 + 1], bz2 = sm[OFF_B5 + 2];
        {
            float2 xa = unpack2(oa0);
            float2 ya = unpack2(oa1);
            out[3 * p0 + 0] = xa.x + bz0;
            out[3 * p0 + 1] = xa.y + bz1;
            out[3 * p0 + 2] = ya.x + bz2;
        }
        if (has1) {
            float2 xb = unpack2(ob0);
            float2 yb = unpack2(ob1);
            out[3 * p1 + 0] = xb.x + bz0;
            out[3 * p1 + 1] = xb.y + bz1;
            out[3 * p1 + 2] = yb.x + bz2;
        }
    }
}

extern "C" void kernel_launch(void* const* d_in, const int* in_sizes, int n_in,
                              void* d_out, int out_size) {
    const float* coords = (const float*)d_in[0];
    const float* Bmat   = (const float*)d_in[1];
    const float* L1     = (const float*)d_in[2];
    const float* R1     = (const float*)d_in[3];
    const float* b1     = (const float*)d_in[4];
    const float* L2     = (const float*)d_in[5];
    const float* R2     = (const float*)d_in[6];
    const float* b2     = (const float*)d_in[7];
    const float* W3     = (const float*)d_in[8];
    const float* b3     = (const float*)d_in[9];
    const float* W4     = (const float*)d_in[10];
    const float* b4     = (const float*)d_in[11];
    const float* W5     = (const float*)d_in[12];
    const float* b5     = (const float*)d_in[13];
    float* out = (float*)d_out;

    const int npts = in_sizes[0] / 2;  // coords is [B,2,H,W]

    int dev = 0;
    cudaGetDevice(&dev);
    int sms = 148;
    cudaDeviceGetAttribute(&sms, cudaDevAttrMultiProcessorCount, dev);

    const size_t smem_bytes = SMEM_FLOATS * sizeof(float);
    cudaFuncSetAttribute(implicit_mlp_kernel,
                         cudaFuncAttributeMaxDynamicSharedMemorySize,
                         (int)smem_bytes);

    implicit_mlp_kernel<<<sms, TPB, smem_bytes>>>(
        coords, Bmat, L1, R1, b1, L2, R2, b2, W3, b3, W4, b4, W5, b5,
        out, npts);
}